// round 12
// baseline (speedup 1.0000x reference)
#include <cuda_runtime.h>
#include <cuda_fp16.h>
#include <cstdint>
#include <math.h>

#define CIN   512
#define COUT  512
#define T_IN  16
#define HWSZ  784           // 28*28
#define THW   12544         // 16*784
#define NB    2
#define WIDTH 28

#define NTILE   3136        // 2 * 8 * 14 * 14 winograd tiles
#define NTPAD   3200        // padded to 25 * 128
#define TPB     1568        // tiles per batch
#define NPTS    64          // 4*4*4 transform points

#define NPOOLS_S 43904      // 1568 + 7840 + 14112 + 20384
#define NPOOLS_PAD 44032
#define WROWS   2520        // per-pool merged: 990 + 750 + 510 + 270
#define WROWS_PAD 2688

// ---------------- scratch (device globals; no allocations allowed) ----------
__device__ float g_xbuf[NB * CIN * THW];               // conv output (relu'd)
__device__ float g_xt[NB * THW * CIN];                 // x transposed [s][c] fp32
__device__ __half g_uh[NPTS * COUT * CIN];             // weights hi [p][co][ci]
__device__ __half g_ul[NPTS * COUT * CIN];             // weights lo
__device__ __half g_vh[(size_t)NPTS * NTPAD * CIN];    // acts fp16 [p][n][ci]
__device__ float g_m[(size_t)NPTS * COUT * NTPAD];     // gemm out [p][co][n]
__device__ __half g_ph[(size_t)NPOOLS_PAD * CIN];      // pools fp16 [s][c]
__device__ __half g_whh[WROWS_PAD * CIN];              // head weights hi (merged)
__device__ __half g_whl[WROWS_PAD * CIN];              // head weights lo
__device__ float g_cls[30 * NPOOLS_S];                 // cls scores, concat

// ---------------- tables ----------------------------------------------------
__constant__ int c_Tp784[4]   = {784, 3920, 7056, 10192};
__constant__ int c_N[4]       = {1568, 7840, 14112, 20384};
__constant__ int c_poolOff[4] = {0, 1568, 9408, 23520};
__constant__ int c_clsOff[4]  = {0, 47040, 282240, 705600};
__constant__ long c_bboxOff[4]= {1317120, 2822400, 8467200, 15240960};
// merged head jobs: rows = [cls 30 | bbox O] per pool
__constant__ int c_hOR[4]    = {990, 750, 510, 270};
__constant__ int c_hwBase[4] = {0, 990, 1740, 2250};
__constant__ int c_hgx[4]    = {13, 62, 111, 160};
__constant__ int c_hstart[5] = {0, 104, 476, 920, 1400};

// ---------------- weight transform: [co][ci][27] -> U[p][co][ci] fp16 hi/lo -
__global__ void wino_w(const float* __restrict__ w) {
    int idx = blockIdx.x * 256 + threadIdx.x;
    if (idx >= COUT * CIN) return;
    int ci = idx & 511;
    int co = idx >> 9;
    float g[27];
#pragma unroll
    for (int k = 0; k < 27; k++) g[k] = w[(size_t)idx * 27 + k];

    float u1[4][9];
#pragma unroll
    for (int i = 0; i < 9; i++) {
        float c0 = g[i], c1 = g[9 + i], c2 = g[18 + i];
        u1[0][i] = c0;
        u1[1][i] = 0.5f * (c0 + c1 + c2);
        u1[2][i] = 0.5f * (c0 - c1 + c2);
        u1[3][i] = c2;
    }
    float u2[4][4][3];
#pragma unroll
    for (int a = 0; a < 4; a++)
#pragma unroll
        for (int kw = 0; kw < 3; kw++) {
            float c0 = u1[a][kw], c1 = u1[a][3 + kw], c2 = u1[a][6 + kw];
            u2[a][0][kw] = c0;
            u2[a][1][kw] = 0.5f * (c0 + c1 + c2);
            u2[a][2][kw] = 0.5f * (c0 - c1 + c2);
            u2[a][3][kw] = c2;
        }
#pragma unroll
    for (int a = 0; a < 4; a++)
#pragma unroll
        for (int bh = 0; bh < 4; bh++) {
            float c0 = u2[a][bh][0], c1 = u2[a][bh][1], c2 = u2[a][bh][2];
            float uw[4];
            uw[0] = c0;
            uw[1] = 0.5f * (c0 + c1 + c2);
            uw[2] = 0.5f * (c0 - c1 + c2);
            uw[3] = c2;
#pragma unroll
            for (int cw = 0; cw < 4; cw++) {
                int p = a * 16 + bh * 4 + cw;
                float v = uw[cw];
                __half hi = __float2half_rn(v);
                float rem = v - __half2float(hi);
                size_t o = ((size_t)p * COUT + co) * CIN + ci;
                g_uh[o] = hi;
                g_ul[o] = __float2half_rn(rem);
            }
        }
}

// ---------------- x [b][c][thw] -> [b*thw][c] fp32 transpose ----------------
__global__ void prep_xt(const float* __restrict__ x) {
    __shared__ float tile[32][33];
    int b  = blockIdx.z;
    int s0 = blockIdx.x * 32;
    int c0 = blockIdx.y * 32;
    for (int i = threadIdx.y; i < 32; i += 8)
        tile[i][threadIdx.x] = x[((size_t)b * CIN + c0 + i) * THW + s0 + threadIdx.x];
    __syncthreads();
    for (int i = threadIdx.y; i < 32; i += 8)
        g_xt[((size_t)b * THW + s0 + i) * CIN + c0 + threadIdx.x] = tile[threadIdx.x][i];
}

// ---------------- input transform: V[p][n][ci] fp16 -------------------------
__global__ __launch_bounds__(256, 1)
void wino_x() {
    const int n  = blockIdx.x;
    const int ci = blockIdx.y * 256 + threadIdx.x;
    float d[64];
    if (n < NTILE) {
        int b  = n / TPB;
        int r  = n - b * TPB;
        int tT = r / 196;
        int r2 = r - tT * 196;
        int tH = r2 / 14;
        int tW = r2 - tH * 14;
        int t0 = 2 * tT - 1, h0 = 2 * tH - 1, w0 = 2 * tW - 1;
#pragma unroll
        for (int dt = 0; dt < 4; dt++) {
            int t = t0 + dt;
#pragma unroll
            for (int dh = 0; dh < 4; dh++) {
                int h = h0 + dh;
#pragma unroll
                for (int dw = 0; dw < 4; dw++) {
                    int w = w0 + dw;
                    int ok = ((unsigned)t < (unsigned)T_IN) & ((unsigned)h < 28u) &
                             ((unsigned)w < 28u);
                    float v = 0.f;
                    if (ok)
                        v = g_xt[((size_t)b * THW + t * HWSZ + h * WIDTH + w) * CIN + ci];
                    d[dt * 16 + dh * 4 + dw] = v;
                }
            }
        }
    } else {
#pragma unroll
        for (int k = 0; k < 64; k++) d[k] = 0.f;
    }
#pragma unroll
    for (int i = 0; i < 16; i++) {
        float a0 = d[i * 4 + 0], a1 = d[i * 4 + 1], a2 = d[i * 4 + 2], a3 = d[i * 4 + 3];
        d[i * 4 + 0] = a0 - a2;
        d[i * 4 + 1] = a1 + a2;
        d[i * 4 + 2] = a2 - a1;
        d[i * 4 + 3] = a1 - a3;
    }
#pragma unroll
    for (int dt = 0; dt < 4; dt++)
#pragma unroll
        for (int dw = 0; dw < 4; dw++) {
            int i0 = dt * 16 + dw;
            float a0 = d[i0], a1 = d[i0 + 4], a2 = d[i0 + 8], a3 = d[i0 + 12];
            d[i0]      = a0 - a2;
            d[i0 + 4]  = a1 + a2;
            d[i0 + 8]  = a2 - a1;
            d[i0 + 12] = a1 - a3;
        }
#pragma unroll
    for (int i = 0; i < 16; i++) {
        float a0 = d[i], a1 = d[i + 16], a2 = d[i + 32], a3 = d[i + 48];
        d[i]      = a0 - a2;
        d[i + 16] = a1 + a2;
        d[i + 32] = a2 - a1;
        d[i + 48] = a1 - a3;
    }
    size_t o = ((size_t)n) * CIN + ci;
    const size_t stride = (size_t)NTPAD * CIN;
#pragma unroll
    for (int p = 0; p < 64; p++) {
        g_vh[o] = __float2half_rn(d[p]);
        o += stride;
    }
}

// ================= mma.sync helpers =========================================
__device__ __forceinline__ uint32_t smem_u32(const void* p) {
    uint32_t a;
    asm("{ .reg .u64 t; cvta.to.shared.u64 t, %1; cvt.u32.u64 %0, t; }"
        : "=r"(a) : "l"(p));
    return a;
}
__device__ __forceinline__ void ldsm_x4(unsigned* r, uint32_t addr) {
    asm volatile("ldmatrix.sync.aligned.m8n8.x4.shared.b16 {%0,%1,%2,%3}, [%4];"
                 : "=r"(r[0]), "=r"(r[1]), "=r"(r[2]), "=r"(r[3]) : "r"(addr));
}
__device__ __forceinline__ void mma16816(float* d, const unsigned* a, const unsigned* b) {
    asm volatile(
        "mma.sync.aligned.m16n8k16.row.col.f32.f16.f16.f32 "
        "{%0,%1,%2,%3}, {%4,%5,%6,%7}, {%8,%9}, {%0,%1,%2,%3};"
        : "+f"(d[0]), "+f"(d[1]), "+f"(d[2]), "+f"(d[3])
        : "r"(a[0]), "r"(a[1]), "r"(a[2]), "r"(a[3]), "r"(b[0]), "r"(b[1]));
}
__device__ __forceinline__ void cp16(uint32_t saddr, const void* gaddr) {
    asm volatile("cp.async.cg.shared.global [%0], [%1], 16;"
                 :: "r"(saddr), "l"(gaddr) : "memory");
}
#define CP_COMMIT()  asm volatile("cp.async.commit_group;" ::: "memory")
#define CP_WAIT1()   asm volatile("cp.async.wait_group 1;" ::: "memory")

#define RSTRIDE 80
#define T_AH 0
#define T_AL 10240
#define T_BH 20480
#define STAGE 30720
#define GEMM_SMEM (STAGE * 3)
#define NKSTEP 16           // K = 512 in chunks of 32

// ---------------- winograd-domain GEMM (fp16 A-split, 3-stage) --------------
__global__ __launch_bounds__(256, 2)
void wino_gemm() {
    extern __shared__ char dsm[];
    const uint32_t base = smem_u32(dsm);

    const int tid  = threadIdx.x;
    const int lane = tid & 31;
    const int wid  = tid >> 5;
    const int wm   = wid & 1;
    const int wn   = wid >> 1;
    const int n0   = blockIdx.x * 128;
    const int co0  = blockIdx.y * 128;
    const int p    = blockIdx.z;

    const int r0 = tid >> 1;          // 0..127
    const int cp = tid & 1;

    auto issue = [&](int j) {
        const int c0 = j << 5;
        const uint32_t sb = base + (j % 3) * STAGE;
#pragma unroll
        for (int e = 0; e < 2; e++) {
            const int q = cp * 2 + e;
            const uint32_t so = (uint32_t)(r0 * RSTRIDE + q * 16);
            const size_t gA = ((size_t)p * COUT + co0 + r0) * CIN + c0 + q * 8;
            cp16(sb + T_AH + so, g_uh + gA);
            cp16(sb + T_AL + so, g_ul + gA);
            const size_t gB = ((size_t)p * NTPAD + n0 + r0) * CIN + c0 + q * 8;
            cp16(sb + T_BH + so, g_vh + gB);
        }
    };

    float acc[4][4][4];
#pragma unroll
    for (int mi = 0; mi < 4; mi++)
#pragma unroll
        for (int ni = 0; ni < 4; ni++)
#pragma unroll
            for (int r = 0; r < 4; r++) acc[mi][ni][r] = 0.f;

    issue(0); CP_COMMIT();
    issue(1); CP_COMMIT();

    const uint32_t aRow  = (uint32_t)((wm * 64 + (lane & 15)) * RSTRIDE)
                         + (uint32_t)((lane >> 4) * 16);
    const uint32_t bRow4 = (uint32_t)((wn * 32 + (lane & 7) + (lane >> 4) * 8) * RSTRIDE)
                         + (uint32_t)(((lane >> 3) & 1) * 16);

    for (int i = 0; i < NKSTEP; i++) {
        CP_WAIT1();
        __syncthreads();
        if (i + 2 < NKSTEP) issue(i + 2);
        CP_COMMIT();

        const uint32_t sb = base + (i % 3) * STAGE;
#pragma unroll
        for (int kk = 0; kk < 2; kk++) {
            const uint32_t kByte = (uint32_t)(kk * 32);
            unsigned ah[4][4], al[4][4], bh[2][4];
#pragma unroll
            for (int mi = 0; mi < 4; mi++) {
                uint32_t ad = sb + aRow + (uint32_t)(mi * 16 * RSTRIDE) + kByte;
                ldsm_x4(ah[mi], ad + T_AH);
                ldsm_x4(al[mi], ad + T_AL);
            }
#pragma unroll
            for (int nip = 0; nip < 2; nip++) {
                uint32_t bd = sb + bRow4 + (uint32_t)(nip * 16 * RSTRIDE) + kByte;
                ldsm_x4(bh[nip], bd + T_BH);
            }
#pragma unroll
            for (int mi = 0; mi < 4; mi++)
#pragma unroll
                for (int nip = 0; nip < 2; nip++) {
                    mma16816(acc[mi][2 * nip],     ah[mi], &bh[nip][0]);
                    mma16816(acc[mi][2 * nip + 1], ah[mi], &bh[nip][2]);
                }
#pragma unroll
            for (int mi = 0; mi < 4; mi++)
#pragma unroll
                for (int nip = 0; nip < 2; nip++) {
                    mma16816(acc[mi][2 * nip],     al[mi], &bh[nip][0]);
                    mma16816(acc[mi][2 * nip + 1], al[mi], &bh[nip][2]);
                }
        }
    }

#pragma unroll
    for (int mi = 0; mi < 4; mi++) {
        const int row0 = co0 + wm * 64 + mi * 16 + (lane >> 2);
        const int row1 = row0 + 8;
#pragma unroll
        for (int ni = 0; ni < 4; ni++) {
            const int col = n0 + wn * 32 + ni * 8 + (lane & 3) * 2;
            float2 o0 = make_float2(acc[mi][ni][0], acc[mi][ni][1]);
            float2 o1 = make_float2(acc[mi][ni][2], acc[mi][ni][3]);
            *(float2*)&g_m[((size_t)p * COUT + row0) * NTPAD + col] = o0;
            *(float2*)&g_m[((size_t)p * COUT + row1) * NTPAD + col] = o1;
        }
    }
}

// ---------------- inverse transform + bias + relu ---------------------------
__global__ __launch_bounds__(256, 1)
void wino_out(const float* __restrict__ bias) {
    const int lane = threadIdx.x & 31;
    const int n  = blockIdx.x * 32 + lane;
    const int co = blockIdx.y * 8 + (threadIdx.x >> 5);

    float m[64];
    {
        size_t o = (size_t)co * NTPAD + n;
        const size_t stride = (size_t)COUT * NTPAD;
#pragma unroll
        for (int pp = 0; pp < 64; pp++) {
            m[pp] = g_m[o];
            o += stride;
        }
    }
    float z[32];
#pragma unroll
    for (int i = 0; i < 16; i++) {
        float m0 = m[i], m1 = m[16 + i], m2 = m[32 + i], m3 = m[48 + i];
        z[i]      = m0 + m1 + m2;
        z[16 + i] = m1 - m2 - m3;
    }
    float y2[16];
#pragma unroll
    for (int a = 0; a < 2; a++)
#pragma unroll
        for (int dw = 0; dw < 4; dw++) {
            int i0 = a * 16 + dw;
            float m0 = z[i0], m1 = z[i0 + 4], m2 = z[i0 + 8], m3 = z[i0 + 12];
            y2[a * 8 + dw]     = m0 + m1 + m2;
            y2[a * 8 + 4 + dw] = m1 - m2 - m3;
        }
    float out[8];
#pragma unroll
    for (int a = 0; a < 2; a++)
#pragma unroll
        for (int b2 = 0; b2 < 2; b2++) {
            int i0 = a * 8 + b2 * 4;
            out[a * 4 + b2 * 2 + 0] = y2[i0] + y2[i0 + 1] + y2[i0 + 2];
            out[a * 4 + b2 * 2 + 1] = y2[i0 + 1] - y2[i0 + 2] - y2[i0 + 3];
        }

    const float bv = bias[co];
    int b  = n / TPB;
    int r  = n - b * TPB;
    int tT = r / 196;
    int r2 = r - tT * 196;
    int tH = r2 / 14;
    int tW = r2 - tH * 14;
    int t = 2 * tT, h = 2 * tH, w = 2 * tW;
    float* dst = g_xbuf + ((size_t)b * CIN + co) * THW;
#pragma unroll
    for (int dt = 0; dt < 2; dt++)
#pragma unroll
        for (int dh = 0; dh < 2; dh++) {
            float2 v;
            v.x = fmaxf(out[dt * 4 + dh * 2 + 0] + bv, 0.f);
            v.y = fmaxf(out[dt * 4 + dh * 2 + 1] + bv, 0.f);
            *(float2*)&dst[(t + dt) * HWSZ + (h + dh) * WIDTH + w] = v;
        }
}

// ---------------- fused temporal max-pool + transpose + fp16 ----------------
// grid (25, 16, 2), block (32, 32): tx = hw (compute) / c (store)
__global__ __launch_bounds__(1024)
void pool_fuse() {
    __shared__ float sm[32][33];
    const int tx  = threadIdx.x;
    const int ty  = threadIdx.y;
    const int b   = blockIdx.z;
    const int hw0 = blockIdx.x * 32;
    const int c0  = blockIdx.y * 32;
    const int hw  = hw0 + tx;

    float v[16];
    const float* src = g_xbuf + ((size_t)b * CIN + c0 + ty) * THW + hw;
    const bool ldok = hw < HWSZ;
#pragma unroll
    for (int t = 0; t < 16; t++) v[t] = ldok ? src[t * HWSZ] : 0.f;

    const int kpool[4] = {16, 12, 8, 4};
    const int tpn[4]   = {1, 5, 9, 13};
    const bool stok = (hw0 + ty) < HWSZ;
#pragma unroll
    for (int p = 0; p < 4; p++) {
        const int T784  = c_Tp784[p];
        const int sBase = c_poolOff[p] + b * T784 + hw0;
        for (int tp = 0; tp < tpn[p]; tp++) {
            float m = v[tp];
            for (int d = 1; d < kpool[p]; d++) m = fmaxf(m, v[tp + d]);
            __syncthreads();
            sm[ty][tx] = m;
            __syncthreads();
            if (stok)
                g_ph[(size_t)(sBase + tp * HWSZ + ty) * CIN + c0 + tx] =
                    __float2half_rn(sm[tx][ty]);
        }
    }
}

// ---------------- head weight convert: per-pool merged rows, fp16 hi/lo -----
__global__ void prep_wh(const float* __restrict__ Wcls, const float* __restrict__ W0,
                        const float* __restrict__ W1, const float* __restrict__ W2,
                        const float* __restrict__ W3) {
    int idx = blockIdx.x * 256 + threadIdx.x;
    if (idx >= WROWS * CIN) return;
    int c   = idx & 511;
    int row = idx >> 9;
    int p;
    if (row < 990)       p = 0;
    else if (row < 1740) p = 1;
    else if (row < 2250) p = 2;
    else                 p = 3;
    const int base = (p == 0) ? 0 : (p == 1) ? 990 : (p == 2) ? 1740 : 2250;
    int lr = row - base;
    const float* src;
    int sr;
    if (lr < 30) { src = Wcls; sr = lr; }
    else {
        src = (p == 0) ? W0 : (p == 1) ? W1 : (p == 2) ? W2 : W3;
        sr = lr - 30;
    }
    float v = src[(size_t)sr * CIN + c];
    __half hi = __float2half_rn(v);
    float rem = v - __half2float(hi);
    g_whh[idx] = hi;
    g_whl[idx] = __float2half_rn(rem);
}

// ---------------- merged head GEMM (BM=128, fp16 A-split, 3-stage) ----------
__global__ __launch_bounds__(256, 2)
void head_mma(float* __restrict__ dout,
              const float* __restrict__ bcls, const float* __restrict__ b0,
              const float* __restrict__ b1,   const float* __restrict__ b2,
              const float* __restrict__ b3) {
    extern __shared__ char dsm[];
    const uint32_t base = smem_u32(dsm);

    int p = 0;
#pragma unroll
    for (int t = 1; t < 4; t++)
        if ((int)blockIdx.x >= c_hstart[t]) p = t;
    const int gx    = c_hgx[p];
    const int local = blockIdx.x - c_hstart[p];
    const int by    = local / gx;
    const int bx    = local - by * gx;
    const int s0    = bx * 128;
    const int o0    = by * 128;
    const int wB    = c_hwBase[p];
    const int OR    = c_hOR[p];
    const int N     = c_N[p];
    const int T784  = c_Tp784[p];
    const int sGlob = c_poolOff[p] + s0;

    const int tid  = threadIdx.x;
    const int lane = tid & 31;
    const int wid  = tid >> 5;
    const int wm   = wid & 1;
    const int wn   = wid >> 1;

    const int r0 = tid >> 1;
    const int cq = tid & 1;

    auto issue = [&](int j) {
        const int c0 = j << 5;
        const uint32_t sb = base + (j % 3) * STAGE;
#pragma unroll
        for (int e = 0; e < 2; e++) {
            const int q = cq * 2 + e;
            const uint32_t so = (uint32_t)(r0 * RSTRIDE + q * 16);
            const size_t gA = (size_t)(wB + o0 + r0) * CIN + c0 + q * 8;
            cp16(sb + T_AH + so, g_whh + gA);
            cp16(sb + T_AL + so, g_whl + gA);
            const size_t gB = (size_t)(sGlob + r0) * CIN + c0 + q * 8;
            cp16(sb + T_BH + so, g_ph + gB);
        }
    };

    float acc[4][4][4];
#pragma unroll
    for (int mi = 0; mi < 4; mi++)
#pragma unroll
        for (int ni = 0; ni < 4; ni++)
#pragma unroll
            for (int r = 0; r < 4; r++) acc[mi][ni][r] = 0.f;

    issue(0); CP_COMMIT();
    issue(1); CP_COMMIT();

    const uint32_t aRow  = (uint32_t)((wm * 64 + (lane & 15)) * RSTRIDE)
                         + (uint32_t)((lane >> 4) * 16);
    const uint32_t bRow4 = (uint32_t)((wn * 32 + (lane & 7) + (lane >> 4) * 8) * RSTRIDE)
                         + (uint32_t)(((lane >> 3) & 1) * 16);

    for (int i = 0; i < NKSTEP; i++) {
        CP_WAIT1();
        __syncthreads();
        if (i + 2 < NKSTEP) issue(i + 2);
        CP_COMMIT();

        const uint32_t sb = base + (i % 3) * STAGE;
#pragma unroll
        for (int kk = 0; kk < 2; kk++) {
            const uint32_t kByte = (uint32_t)(kk * 32);
            unsigned ah[4][4], al[4][4], bh[2][4];
#pragma unroll
            for (int mi = 0; mi < 4; mi++) {
                uint32_t ad = sb + aRow + (uint32_t)(mi * 16 * RSTRIDE) + kByte;
                ldsm_x4(ah[mi], ad + T_AH);
                ldsm_x4(al[mi], ad + T_AL);
            }
#pragma unroll
            for (int nip = 0; nip < 2; nip++) {
                uint32_t bd = sb + bRow4 + (uint32_t)(nip * 16 * RSTRIDE) + kByte;
                ldsm_x4(bh[nip], bd + T_BH);
            }
#pragma unroll
            for (int mi = 0; mi < 4; mi++)
#pragma unroll
                for (int nip = 0; nip < 2; nip++) {
                    mma16816(acc[mi][2 * nip],     ah[mi], &bh[nip][0]);
                    mma16816(acc[mi][2 * nip + 1], ah[mi], &bh[nip][2]);
                }
#pragma unroll
            for (int mi = 0; mi < 4; mi++)
#pragma unroll
                for (int nip = 0; nip < 2; nip++) {
                    mma16816(acc[mi][2 * nip],     al[mi], &bh[nip][0]);
                    mma16816(acc[mi][2 * nip + 1], al[mi], &bh[nip][2]);
                }
        }
    }

    const float* bbb = (p == 0) ? b0 : (p == 1) ? b1 : (p == 2) ? b2 : b3;
    const int Obb = OR - 30;

#pragma unroll
    for (int mi = 0; mi < 4; mi++) {
#pragma unroll
        for (int half = 0; half < 2; half++) {
            const int lr = o0 + wm * 64 + mi * 16 + half * 8 + (lane >> 2);
            if (lr >= OR) continue;
            const float bv = (lr < 30) ? bcls[lr] : bbb[lr - 30];
#pragma unroll
            for (int ni = 0; ni < 4; ni++) {
#pragma unroll
                for (int e = 0; e < 2; e++) {
                    const int s = s0 + wn * 32 + ni * 8 + (lane & 3) * 2 + e;
                    if (s >= N) continue;
                    const float r = acc[mi][ni][half * 2 + e] + bv;
                    if (lr < 30) {
                        g_cls[c_clsOff[p] + lr * N + s] = r;
                    } else {
                        const int o  = lr - 30;
                        const int bb = s >= T784 ? 1 : 0;
                        const int rr = s - bb * T784;
                        dout[c_bboxOff[p] + (size_t)bb * Obb * T784 +
                             (size_t)o * T784 + rr] = r;
                    }
                }
            }
        }
    }
}

// ---------------- combined softmax over all pools ---------------------------
__global__ void softmax_all(float* __restrict__ out) {
    int idx = blockIdx.x * 256 + threadIdx.x;
    if (idx >= 658560) return;
    int p, local;
    if (idx < 23520)        { p = 0; local = idx; }
    else if (idx < 141120)  { p = 1; local = idx - 23520; }
    else if (idx < 352800)  { p = 2; local = idx - 141120; }
    else                    { p = 3; local = idx - 352800; }
    const int N = c_N[p];
    const int T784 = c_Tp784[p];
    int c  = local / N;
    int ss = local - c * N;
    const float* cls = g_cls + c_clsOff[p];
    float v0 = cls[c * N + ss];
    float v1 = cls[(c + 15) * N + ss];
    float mx = fmaxf(v0, v1);
    float e0 = expf(v0 - mx), e1 = expf(v1 - mx);
    float inv = 1.f / (e0 + e1);
    int b = ss >= T784 ? 1 : 0;
    int r = ss - b * T784;
    long po = (p == 0) ? 0L : (p == 1) ? 47040L : (p == 2) ? 282240L : 705600L;
    out[po + (size_t)b * 30 * T784 + (size_t)c * T784 + r]        = e0 * inv;
    out[po + (size_t)b * 30 * T784 + (size_t)(c + 15) * T784 + r] = e1 * inv;
}

// ---------------- launch -----------------------------------------------------
extern "C" void kernel_launch(void* const* d_in, const int* in_sizes, int n_in,
                              void* d_out, int out_size) {
    const float* base  = (const float*)d_in[0];
    const float* Wc    = (const float*)d_in[4];
    const float* bc    = (const float*)d_in[5];
    const float* Wcls  = (const float*)d_in[6];
    const float* bcls  = (const float*)d_in[7];
    const float* Wbb[4] = {(const float*)d_in[8],  (const float*)d_in[10],
                           (const float*)d_in[12], (const float*)d_in[14]};
    const float* bbb[4] = {(const float*)d_in[9],  (const float*)d_in[11],
                           (const float*)d_in[13], (const float*)d_in[15]};
    float* out = (float*)d_out;

    cudaFuncSetAttribute(wino_gemm, cudaFuncAttributeMaxDynamicSharedMemorySize,
                         GEMM_SMEM);
    cudaFuncSetAttribute(head_mma, cudaFuncAttributeMaxDynamicSharedMemorySize,
                         GEMM_SMEM);

    wino_w<<<(COUT * CIN + 255) / 256, 256>>>(Wc);
    prep_wh<<<(WROWS * CIN + 255) / 256, 256>>>(Wcls, Wbb[0], Wbb[1], Wbb[2], Wbb[3]);
    prep_xt<<<dim3(THW / 32, CIN / 32, NB), dim3(32, 8)>>>(base);
    wino_x<<<dim3(NTPAD, 2), 256>>>();
    wino_gemm<<<dim3(NTPAD / 128, COUT / 128, NPTS), 256, GEMM_SMEM>>>();
    wino_out<<<dim3(NTILE / 32, COUT / 8), 256>>>(bc);
    pool_fuse<<<dim3(25, 16, 2), dim3(32, 32)>>>();
    head_mma<<<1400, 256, GEMM_SMEM>>>(out, bcls, bbb[0], bbb[1], bbb[2], bbb[3]);
    softmax_all<<<(658560 + 255) / 256, 256>>>(out);
}

// round 15
// speedup vs baseline: 1.3905x; 1.3905x over previous
#include <cuda_runtime.h>
#include <cuda_fp16.h>
#include <cstdint>
#include <math.h>

#define CIN   512
#define COUT  512
#define T_IN  16
#define HWSZ  784           // 28*28
#define THW   12544         // 16*784
#define NB    2
#define WIDTH 28

#define NTILE   3136        // 2 * 8 * 14 * 14 winograd tiles
#define NTPAD   3200        // padded to 25 * 128
#define TPB     1568        // tiles per batch
#define NPTS    64          // 4*4*4 transform points

#define NPOOLS_S 43904      // 1568 + 7840 + 14112 + 20384
#define NPOOLS_PAD 44032
#define WROWS   2520        // per-pool merged: 990 + 750 + 510 + 270
#define WROWS_PAD 2688

// ---------------- scratch (device globals; no allocations allowed) ----------
__device__ float g_xbuf[NB * CIN * THW];               // conv output (relu'd)
__device__ float g_xt[NB * THW * CIN];                 // x transposed [s][c] fp32
__device__ __half g_uh[NPTS * COUT * CIN];             // weights fp16 [p][co][ci]
__device__ __half g_vh[(size_t)NPTS * NTPAD * CIN];    // acts fp16 [p][n][ci]
__device__ float g_m[(size_t)NPTS * COUT * NTPAD];     // gemm out [p][co][n]
__device__ __half g_ph[(size_t)NPOOLS_PAD * CIN];      // pools fp16 [s][c]
__device__ __half g_whh[WROWS_PAD * CIN];              // head weights hi (merged)
__device__ __half g_whl[WROWS_PAD * CIN];              // head weights lo
__device__ float g_cls[30 * NPOOLS_S];                 // cls scores, concat

// ---------------- tables ----------------------------------------------------
__constant__ int c_Tp784[4]   = {784, 3920, 7056, 10192};
__constant__ int c_N[4]       = {1568, 7840, 14112, 20384};
__constant__ int c_poolOff[4] = {0, 1568, 9408, 23520};
__constant__ int c_clsOff[4]  = {0, 47040, 282240, 705600};
__constant__ long c_bboxOff[4]= {1317120, 2822400, 8467200, 15240960};
// merged head jobs: rows = [cls 30 | bbox O] per pool
__constant__ int c_hOR[4]    = {990, 750, 510, 270};
__constant__ int c_hwBase[4] = {0, 990, 1740, 2250};
__constant__ int c_hgx[4]    = {13, 62, 111, 160};
__constant__ int c_hstart[5] = {0, 104, 476, 920, 1400};

// ---------------- weight transform: [co][ci][27] -> U[p][co][ci] fp16 -------
__global__ void wino_w(const float* __restrict__ w) {
    int idx = blockIdx.x * 256 + threadIdx.x;
    if (idx >= COUT * CIN) return;
    int ci = idx & 511;
    int co = idx >> 9;
    float g[27];
#pragma unroll
    for (int k = 0; k < 27; k++) g[k] = w[(size_t)idx * 27 + k];

    float u1[4][9];
#pragma unroll
    for (int i = 0; i < 9; i++) {
        float c0 = g[i], c1 = g[9 + i], c2 = g[18 + i];
        u1[0][i] = c0;
        u1[1][i] = 0.5f * (c0 + c1 + c2);
        u1[2][i] = 0.5f * (c0 - c1 + c2);
        u1[3][i] = c2;
    }
    float u2[4][4][3];
#pragma unroll
    for (int a = 0; a < 4; a++)
#pragma unroll
        for (int kw = 0; kw < 3; kw++) {
            float c0 = u1[a][kw], c1 = u1[a][3 + kw], c2 = u1[a][6 + kw];
            u2[a][0][kw] = c0;
            u2[a][1][kw] = 0.5f * (c0 + c1 + c2);
            u2[a][2][kw] = 0.5f * (c0 - c1 + c2);
            u2[a][3][kw] = c2;
        }
#pragma unroll
    for (int a = 0; a < 4; a++)
#pragma unroll
        for (int bh = 0; bh < 4; bh++) {
            float c0 = u2[a][bh][0], c1 = u2[a][bh][1], c2 = u2[a][bh][2];
            float uw[4];
            uw[0] = c0;
            uw[1] = 0.5f * (c0 + c1 + c2);
            uw[2] = 0.5f * (c0 - c1 + c2);
            uw[3] = c2;
#pragma unroll
            for (int cw = 0; cw < 4; cw++) {
                int p = a * 16 + bh * 4 + cw;
                size_t o = ((size_t)p * COUT + co) * CIN + ci;
                g_uh[o] = __float2half_rn(uw[cw]);
            }
        }
}

// ---------------- x [b][c][thw] -> [b*thw][c] fp32 transpose ----------------
__global__ void prep_xt(const float* __restrict__ x) {
    __shared__ float tile[32][33];
    int b  = blockIdx.z;
    int s0 = blockIdx.x * 32;
    int c0 = blockIdx.y * 32;
    for (int i = threadIdx.y; i < 32; i += 8)
        tile[i][threadIdx.x] = x[((size_t)b * CIN + c0 + i) * THW + s0 + threadIdx.x];
    __syncthreads();
    for (int i = threadIdx.y; i < 32; i += 8)
        g_xt[((size_t)b * THW + s0 + i) * CIN + c0 + threadIdx.x] = tile[threadIdx.x][i];
}

// ---------------- input transform: V[p][n][ci] fp16 -------------------------
__global__ __launch_bounds__(256, 1)
void wino_x() {
    const int n  = blockIdx.x;
    const int ci = blockIdx.y * 256 + threadIdx.x;
    float d[64];
    if (n < NTILE) {
        int b  = n / TPB;
        int r  = n - b * TPB;
        int tT = r / 196;
        int r2 = r - tT * 196;
        int tH = r2 / 14;
        int tW = r2 - tH * 14;
        int t0 = 2 * tT - 1, h0 = 2 * tH - 1, w0 = 2 * tW - 1;
#pragma unroll
        for (int dt = 0; dt < 4; dt++) {
            int t = t0 + dt;
#pragma unroll
            for (int dh = 0; dh < 4; dh++) {
                int h = h0 + dh;
#pragma unroll
                for (int dw = 0; dw < 4; dw++) {
                    int w = w0 + dw;
                    int ok = ((unsigned)t < (unsigned)T_IN) & ((unsigned)h < 28u) &
                             ((unsigned)w < 28u);
                    float v = 0.f;
                    if (ok)
                        v = g_xt[((size_t)b * THW + t * HWSZ + h * WIDTH + w) * CIN + ci];
                    d[dt * 16 + dh * 4 + dw] = v;
                }
            }
        }
    } else {
#pragma unroll
        for (int k = 0; k < 64; k++) d[k] = 0.f;
    }
#pragma unroll
    for (int i = 0; i < 16; i++) {
        float a0 = d[i * 4 + 0], a1 = d[i * 4 + 1], a2 = d[i * 4 + 2], a3 = d[i * 4 + 3];
        d[i * 4 + 0] = a0 - a2;
        d[i * 4 + 1] = a1 + a2;
        d[i * 4 + 2] = a2 - a1;
        d[i * 4 + 3] = a1 - a3;
    }
#pragma unroll
    for (int dt = 0; dt < 4; dt++)
#pragma unroll
        for (int dw = 0; dw < 4; dw++) {
            int i0 = dt * 16 + dw;
            float a0 = d[i0], a1 = d[i0 + 4], a2 = d[i0 + 8], a3 = d[i0 + 12];
            d[i0]      = a0 - a2;
            d[i0 + 4]  = a1 + a2;
            d[i0 + 8]  = a2 - a1;
            d[i0 + 12] = a1 - a3;
        }
#pragma unroll
    for (int i = 0; i < 16; i++) {
        float a0 = d[i], a1 = d[i + 16], a2 = d[i + 32], a3 = d[i + 48];
        d[i]      = a0 - a2;
        d[i + 16] = a1 + a2;
        d[i + 32] = a2 - a1;
        d[i + 48] = a1 - a3;
    }
    size_t o = ((size_t)n) * CIN + ci;
    const size_t stride = (size_t)NTPAD * CIN;
#pragma unroll
    for (int p = 0; p < 64; p++) {
        g_vh[o] = __float2half_rn(d[p]);
        o += stride;
    }
}

// ================= mma.sync helpers =========================================
__device__ __forceinline__ uint32_t smem_u32(const void* p) {
    uint32_t a;
    asm("{ .reg .u64 t; cvta.to.shared.u64 t, %1; cvt.u32.u64 %0, t; }"
        : "=r"(a) : "l"(p));
    return a;
}
__device__ __forceinline__ void ldsm_x4(unsigned* r, uint32_t addr) {
    asm volatile("ldmatrix.sync.aligned.m8n8.x4.shared.b16 {%0,%1,%2,%3}, [%4];"
                 : "=r"(r[0]), "=r"(r[1]), "=r"(r[2]), "=r"(r[3]) : "r"(addr));
}
__device__ __forceinline__ void mma16816(float* d, const unsigned* a, const unsigned* b) {
    asm volatile(
        "mma.sync.aligned.m16n8k16.row.col.f32.f16.f16.f32 "
        "{%0,%1,%2,%3}, {%4,%5,%6,%7}, {%8,%9}, {%0,%1,%2,%3};"
        : "+f"(d[0]), "+f"(d[1]), "+f"(d[2]), "+f"(d[3])
        : "r"(a[0]), "r"(a[1]), "r"(a[2]), "r"(a[3]), "r"(b[0]), "r"(b[1]));
}
__device__ __forceinline__ void cp16(uint32_t saddr, const void* gaddr) {
    asm volatile("cp.async.cg.shared.global [%0], [%1], 16;"
                 :: "r"(saddr), "l"(gaddr) : "memory");
}
#define CP_COMMIT()  asm volatile("cp.async.commit_group;" ::: "memory")
#define CP_WAIT1()   asm volatile("cp.async.wait_group 1;" ::: "memory")

#define RSTRIDE 80
// conv stages: A single plane + B plane
#define C_AH 0
#define C_BH 10240
#define CSTAGE 20480
#define CONV_SMEM (CSTAGE * 3)
// head stages: A hi/lo + B
#define T_AH 0
#define T_AL 10240
#define T_BH 20480
#define STAGE 30720
#define HEAD_SMEM (STAGE * 3)
#define NKSTEP 16           // K = 512 in chunks of 32

// ---------------- winograd-domain GEMM (single fp16, 3-stage) ---------------
__global__ __launch_bounds__(256, 2)
void wino_gemm() {
    extern __shared__ char dsm[];
    const uint32_t base = smem_u32(dsm);

    const int tid  = threadIdx.x;
    const int lane = tid & 31;
    const int wid  = tid >> 5;
    const int wm   = wid & 1;
    const int wn   = wid >> 1;
    const int n0   = blockIdx.x * 128;
    const int co0  = blockIdx.y * 128;
    const int p    = blockIdx.z;

    const int r0 = tid >> 1;          // 0..127
    const int cp = tid & 1;

    auto issue = [&](int j) {
        const int c0 = j << 5;
        const uint32_t sb = base + (j % 3) * CSTAGE;
#pragma unroll
        for (int e = 0; e < 2; e++) {
            const int q = cp * 2 + e;
            const uint32_t so = (uint32_t)(r0 * RSTRIDE + q * 16);
            const size_t gA = ((size_t)p * COUT + co0 + r0) * CIN + c0 + q * 8;
            cp16(sb + C_AH + so, g_uh + gA);
            const size_t gB = ((size_t)p * NTPAD + n0 + r0) * CIN + c0 + q * 8;
            cp16(sb + C_BH + so, g_vh + gB);
        }
    };

    float acc[4][4][4];
#pragma unroll
    for (int mi = 0; mi < 4; mi++)
#pragma unroll
        for (int ni = 0; ni < 4; ni++)
#pragma unroll
            for (int r = 0; r < 4; r++) acc[mi][ni][r] = 0.f;

    issue(0); CP_COMMIT();
    issue(1); CP_COMMIT();

    const uint32_t aRow  = (uint32_t)((wm * 64 + (lane & 15)) * RSTRIDE)
                         + (uint32_t)((lane >> 4) * 16);
    const uint32_t bRow4 = (uint32_t)((wn * 32 + (lane & 7) + (lane >> 4) * 8) * RSTRIDE)
                         + (uint32_t)(((lane >> 3) & 1) * 16);

    for (int i = 0; i < NKSTEP; i++) {
        CP_WAIT1();
        __syncthreads();
        if (i + 2 < NKSTEP) issue(i + 2);
        CP_COMMIT();

        const uint32_t sb = base + (i % 3) * CSTAGE;
#pragma unroll
        for (int kk = 0; kk < 2; kk++) {
            const uint32_t kByte = (uint32_t)(kk * 32);
            unsigned ah[4][4], bh[2][4];
#pragma unroll
            for (int mi = 0; mi < 4; mi++) {
                uint32_t ad = sb + aRow + (uint32_t)(mi * 16 * RSTRIDE) + kByte;
                ldsm_x4(ah[mi], ad + C_AH);
            }
#pragma unroll
            for (int nip = 0; nip < 2; nip++) {
                uint32_t bd = sb + bRow4 + (uint32_t)(nip * 16 * RSTRIDE) + kByte;
                ldsm_x4(bh[nip], bd + C_BH);
            }
#pragma unroll
            for (int mi = 0; mi < 4; mi++)
#pragma unroll
                for (int nip = 0; nip < 2; nip++) {
                    mma16816(acc[mi][2 * nip],     ah[mi], &bh[nip][0]);
                    mma16816(acc[mi][2 * nip + 1], ah[mi], &bh[nip][2]);
                }
        }
    }

#pragma unroll
    for (int mi = 0; mi < 4; mi++) {
        const int row0 = co0 + wm * 64 + mi * 16 + (lane >> 2);
        const int row1 = row0 + 8;
#pragma unroll
        for (int ni = 0; ni < 4; ni++) {
            const int col = n0 + wn * 32 + ni * 8 + (lane & 3) * 2;
            float2 o0 = make_float2(acc[mi][ni][0], acc[mi][ni][1]);
            float2 o1 = make_float2(acc[mi][ni][2], acc[mi][ni][3]);
            *(float2*)&g_m[((size_t)p * COUT + row0) * NTPAD + col] = o0;
            *(float2*)&g_m[((size_t)p * COUT + row1) * NTPAD + col] = o1;
        }
    }
}

// ---------------- inverse transform + bias + relu ---------------------------
__global__ __launch_bounds__(256, 1)
void wino_out(const float* __restrict__ bias) {
    const int lane = threadIdx.x & 31;
    const int n  = blockIdx.x * 32 + lane;
    const int co = blockIdx.y * 8 + (threadIdx.x >> 5);

    float m[64];
    {
        size_t o = (size_t)co * NTPAD + n;
        const size_t stride = (size_t)COUT * NTPAD;
#pragma unroll
        for (int pp = 0; pp < 64; pp++) {
            m[pp] = g_m[o];
            o += stride;
        }
    }
    float z[32];
#pragma unroll
    for (int i = 0; i < 16; i++) {
        float m0 = m[i], m1 = m[16 + i], m2 = m[32 + i], m3 = m[48 + i];
        z[i]      = m0 + m1 + m2;
        z[16 + i] = m1 - m2 - m3;
    }
    float y2[16];
#pragma unroll
    for (int a = 0; a < 2; a++)
#pragma unroll
        for (int dw = 0; dw < 4; dw++) {
            int i0 = a * 16 + dw;
            float m0 = z[i0], m1 = z[i0 + 4], m2 = z[i0 + 8], m3 = z[i0 + 12];
            y2[a * 8 + dw]     = m0 + m1 + m2;
            y2[a * 8 + 4 + dw] = m1 - m2 - m3;
        }
    float out[8];
#pragma unroll
    for (int a = 0; a < 2; a++)
#pragma unroll
        for (int b2 = 0; b2 < 2; b2++) {
            int i0 = a * 8 + b2 * 4;
            out[a * 4 + b2 * 2 + 0] = y2[i0] + y2[i0 + 1] + y2[i0 + 2];
            out[a * 4 + b2 * 2 + 1] = y2[i0 + 1] - y2[i0 + 2] - y2[i0 + 3];
        }

    const float bv = bias[co];
    int b  = n / TPB;
    int r  = n - b * TPB;
    int tT = r / 196;
    int r2 = r - tT * 196;
    int tH = r2 / 14;
    int tW = r2 - tH * 14;
    int t = 2 * tT, h = 2 * tH, w = 2 * tW;
    float* dst = g_xbuf + ((size_t)b * CIN + co) * THW;
#pragma unroll
    for (int dt = 0; dt < 2; dt++)
#pragma unroll
        for (int dh = 0; dh < 2; dh++) {
            float2 v;
            v.x = fmaxf(out[dt * 4 + dh * 2 + 0] + bv, 0.f);
            v.y = fmaxf(out[dt * 4 + dh * 2 + 1] + bv, 0.f);
            *(float2*)&dst[(t + dt) * HWSZ + (h + dh) * WIDTH + w] = v;
        }
}

// ---------------- fused temporal max-pool + transpose + fp16 ----------------
__global__ __launch_bounds__(1024)
void pool_fuse() {
    __shared__ float sm[32][33];
    const int tx  = threadIdx.x;
    const int ty  = threadIdx.y;
    const int b   = blockIdx.z;
    const int hw0 = blockIdx.x * 32;
    const int c0  = blockIdx.y * 32;
    const int hw  = hw0 + tx;

    float v[16];
    const float* src = g_xbuf + ((size_t)b * CIN + c0 + ty) * THW + hw;
    const bool ldok = hw < HWSZ;
#pragma unroll
    for (int t = 0; t < 16; t++) v[t] = ldok ? src[t * HWSZ] : 0.f;

    const int kpool[4] = {16, 12, 8, 4};
    const int tpn[4]   = {1, 5, 9, 13};
    const bool stok = (hw0 + ty) < HWSZ;
#pragma unroll
    for (int p = 0; p < 4; p++) {
        const int T784  = c_Tp784[p];
        const int sBase = c_poolOff[p] + b * T784 + hw0;
        for (int tp = 0; tp < tpn[p]; tp++) {
            float m = v[tp];
            for (int d = 1; d < kpool[p]; d++) m = fmaxf(m, v[tp + d]);
            __syncthreads();
            sm[ty][tx] = m;
            __syncthreads();
            if (stok)
                g_ph[(size_t)(sBase + tp * HWSZ + ty) * CIN + c0 + tx] =
                    __float2half_rn(sm[tx][ty]);
        }
    }
}

// ---------------- head weight convert: per-pool merged rows, fp16 hi/lo -----
__global__ void prep_wh(const float* __restrict__ Wcls, const float* __restrict__ W0,
                        const float* __restrict__ W1, const float* __restrict__ W2,
                        const float* __restrict__ W3) {
    int idx = blockIdx.x * 256 + threadIdx.x;
    if (idx >= WROWS * CIN) return;
    int c   = idx & 511;
    int row = idx >> 9;
    int p;
    if (row < 990)       p = 0;
    else if (row < 1740) p = 1;
    else if (row < 2250) p = 2;
    else                 p = 3;
    const int base = (p == 0) ? 0 : (p == 1) ? 990 : (p == 2) ? 1740 : 2250;
    int lr = row - base;
    const float* src;
    int sr;
    if (lr < 30) { src = Wcls; sr = lr; }
    else {
        src = (p == 0) ? W0 : (p == 1) ? W1 : (p == 2) ? W2 : W3;
        sr = lr - 30;
    }
    float v = src[(size_t)sr * CIN + c];
    __half hi = __float2half_rn(v);
    float rem = v - __half2float(hi);
    g_whh[idx] = hi;
    g_whl[idx] = __float2half_rn(rem);
}

// ---------------- merged head GEMM (BM=128, fp16 A-split, 3-stage) ----------
__global__ __launch_bounds__(256, 2)
void head_mma(float* __restrict__ dout,
              const float* __restrict__ bcls, const float* __restrict__ b0,
              const float* __restrict__ b1,   const float* __restrict__ b2,
              const float* __restrict__ b3) {
    extern __shared__ char dsm[];
    const uint32_t base = smem_u32(dsm);

    int p = 0;
#pragma unroll
    for (int t = 1; t < 4; t++)
        if ((int)blockIdx.x >= c_hstart[t]) p = t;
    const int gx    = c_hgx[p];
    const int local = blockIdx.x - c_hstart[p];
    const int by    = local / gx;
    const int bx    = local - by * gx;
    const int s0    = bx * 128;
    const int o0    = by * 128;
    const int wB    = c_hwBase[p];
    const int OR    = c_hOR[p];
    const int N     = c_N[p];
    const int T784  = c_Tp784[p];
    const int sGlob = c_poolOff[p] + s0;

    const int tid  = threadIdx.x;
    const int lane = tid & 31;
    const int wid  = tid >> 5;
    const int wm   = wid & 1;
    const int wn   = wid >> 1;

    const int r0 = tid >> 1;
    const int cq = tid & 1;

    auto issue = [&](int j) {
        const int c0 = j << 5;
        const uint32_t sb = base + (j % 3) * STAGE;
#pragma unroll
        for (int e = 0; e < 2; e++) {
            const int q = cq * 2 + e;
            const uint32_t so = (uint32_t)(r0 * RSTRIDE + q * 16);
            const size_t gA = (size_t)(wB + o0 + r0) * CIN + c0 + q * 8;
            cp16(sb + T_AH + so, g_whh + gA);
            cp16(sb + T_AL + so, g_whl + gA);
            const size_t gB = (size_t)(sGlob + r0) * CIN + c0 + q * 8;
            cp16(sb + T_BH + so, g_ph + gB);
        }
    };

    float acc[4][4][4];
#pragma unroll
    for (int mi = 0; mi < 4; mi++)
#pragma unroll
        for (int ni = 0; ni < 4; ni++)
#pragma unroll
            for (int r = 0; r < 4; r++) acc[mi][ni][r] = 0.f;

    issue(0); CP_COMMIT();
    issue(1); CP_COMMIT();

    const uint32_t aRow  = (uint32_t)((wm * 64 + (lane & 15)) * RSTRIDE)
                         + (uint32_t)((lane >> 4) * 16);
    const uint32_t bRow4 = (uint32_t)((wn * 32 + (lane & 7) + (lane >> 4) * 8) * RSTRIDE)
                         + (uint32_t)(((lane >> 3) & 1) * 16);

    for (int i = 0; i < NKSTEP; i++) {
        CP_WAIT1();
        __syncthreads();
        if (i + 2 < NKSTEP) issue(i + 2);
        CP_COMMIT();

        const uint32_t sb = base + (i % 3) * STAGE;
#pragma unroll
        for (int kk = 0; kk < 2; kk++) {
            const uint32_t kByte = (uint32_t)(kk * 32);
            unsigned ah[4][4], al[4][4], bh[2][4];
#pragma unroll
            for (int mi = 0; mi < 4; mi++) {
                uint32_t ad = sb + aRow + (uint32_t)(mi * 16 * RSTRIDE) + kByte;
                ldsm_x4(ah[mi], ad + T_AH);
                ldsm_x4(al[mi], ad + T_AL);
            }
#pragma unroll
            for (int nip = 0; nip < 2; nip++) {
                uint32_t bd = sb + bRow4 + (uint32_t)(nip * 16 * RSTRIDE) + kByte;
                ldsm_x4(bh[nip], bd + T_BH);
            }
#pragma unroll
            for (int mi = 0; mi < 4; mi++)
#pragma unroll
                for (int nip = 0; nip < 2; nip++) {
                    mma16816(acc[mi][2 * nip],     ah[mi], &bh[nip][0]);
                    mma16816(acc[mi][2 * nip + 1], ah[mi], &bh[nip][2]);
                }
#pragma unroll
            for (int mi = 0; mi < 4; mi++)
#pragma unroll
                for (int nip = 0; nip < 2; nip++) {
                    mma16816(acc[mi][2 * nip],     al[mi], &bh[nip][0]);
                    mma16816(acc[mi][2 * nip + 1], al[mi], &bh[nip][2]);
                }
        }
    }

    const float* bbb = (p == 0) ? b0 : (p == 1) ? b1 : (p == 2) ? b2 : b3;
    const int Obb = OR - 30;

#pragma unroll
    for (int mi = 0; mi < 4; mi++) {
#pragma unroll
        for (int half = 0; half < 2; half++) {
            const int lr = o0 + wm * 64 + mi * 16 + half * 8 + (lane >> 2);
            if (lr >= OR) continue;
            const float bv = (lr < 30) ? bcls[lr] : bbb[lr - 30];
#pragma unroll
            for (int ni = 0; ni < 4; ni++) {
#pragma unroll
                for (int e = 0; e < 2; e++) {
                    const int s = s0 + wn * 32 + ni * 8 + (lane & 3) * 2 + e;
                    if (s >= N) continue;
                    const float r = acc[mi][ni][half * 2 + e] + bv;
                    if (lr < 30) {
                        g_cls[c_clsOff[p] + lr * N + s] = r;
                    } else {
                        const int o  = lr - 30;
                        const int bb = s >= T784 ? 1 : 0;
                        const int rr = s - bb * T784;
                        dout[c_bboxOff[p] + (size_t)bb * Obb * T784 +
                             (size_t)o * T784 + rr] = r;
                    }
                }
            }
        }
    }
}

// ---------------- combined softmax over all pools ---------------------------
__global__ void softmax_all(float* __restrict__ out) {
    int idx = blockIdx.x * 256 + threadIdx.x;
    if (idx >= 658560) return;
    int p, local;
    if (idx < 23520)        { p = 0; local = idx; }
    else if (idx < 141120)  { p = 1; local = idx - 23520; }
    else if (idx < 352800)  { p = 2; local = idx - 141120; }
    else                    { p = 3; local = idx - 352800; }
    const int N = c_N[p];
    const int T784 = c_Tp784[p];
    int c  = local / N;
    int ss = local - c * N;
    const float* cls = g_cls + c_clsOff[p];
    float v0 = cls[c * N + ss];
    float v1 = cls[(c + 15) * N + ss];
    float mx = fmaxf(v0, v1);
    float e0 = expf(v0 - mx), e1 = expf(v1 - mx);
    float inv = 1.f / (e0 + e1);
    int b = ss >= T784 ? 1 : 0;
    int r = ss - b * T784;
    long po = (p == 0) ? 0L : (p == 1) ? 47040L : (p == 2) ? 282240L : 705600L;
    out[po + (size_t)b * 30 * T784 + (size_t)c * T784 + r]        = e0 * inv;
    out[po + (size_t)b * 30 * T784 + (size_t)(c + 15) * T784 + r] = e1 * inv;
}

// ---------------- launch -----------------------------------------------------
extern "C" void kernel_launch(void* const* d_in, const int* in_sizes, int n_in,
                              void* d_out, int out_size) {
    const float* base  = (const float*)d_in[0];
    const float* Wc    = (const float*)d_in[4];
    const float* bc    = (const float*)d_in[5];
    const float* Wcls  = (const float*)d_in[6];
    const float* bcls  = (const float*)d_in[7];
    const float* Wbb[4] = {(const float*)d_in[8],  (const float*)d_in[10],
                           (const float*)d_in[12], (const float*)d_in[14]};
    const float* bbb[4] = {(const float*)d_in[9],  (const float*)d_in[11],
                           (const float*)d_in[13], (const float*)d_in[15]};
    float* out = (float*)d_out;

    cudaFuncSetAttribute(wino_gemm, cudaFuncAttributeMaxDynamicSharedMemorySize,
                         CONV_SMEM);
    cudaFuncSetAttribute(head_mma, cudaFuncAttributeMaxDynamicSharedMemorySize,
                         HEAD_SMEM);

    wino_w<<<(COUT * CIN + 255) / 256, 256>>>(Wc);
    prep_wh<<<(WROWS * CIN + 255) / 256, 256>>>(Wcls, Wbb[0], Wbb[1], Wbb[2], Wbb[3]);
    prep_xt<<<dim3(THW / 32, CIN / 32, NB), dim3(32, 8)>>>(base);
    wino_x<<<dim3(NTPAD, 2), 256>>>();
    wino_gemm<<<dim3(NTPAD / 128, COUT / 128, NPTS), 256, CONV_SMEM>>>();
    wino_out<<<dim3(NTILE / 32, COUT / 8), 256>>>(bc);
    pool_fuse<<<dim3(25, 16, 2), dim3(32, 32)>>>();
    head_mma<<<1400, 256, HEAD_SMEM>>>(out, bcls, bbb[0], bbb[1], bbb[2], bbb[3]);
    softmax_all<<<(658560 + 255) / 256, 256>>>(out);
}